// round 10
// baseline (speedup 1.0000x reference)
#include <cuda_runtime.h>
#include <math.h>
#include <stdint.h>

// ---------------- problem constants (l = 2, 76x76 head) ----------------
#define IN_H   76
#define IN_W   76
#define PLANE  (IN_H * IN_W)        // 5776 (even)
#define BS     32
#define NT     20
#define NA     3
#define NC     80
#define CELLS  (NA * PLANE)         // 17328 per batch item
#define VCELLS2 (CELLS / 2)         // 8664 float2 groups per batch item
#define NVB    ((VCELLS2 + 255) / 256)  // 34 dense x-blocks
#define TOTAL_BLOCKS ((NVB + 1) * BS)   // 1120
#define NBANK  16

__device__ __constant__ float c_aw9[9] = {1.5f, 2.375f, 5.f, 4.5f, 9.5f, 9.f, 17.75f, 24.f, 57.375f};
__device__ __constant__ float c_ah9[9] = {2.f, 4.5f, 3.5f, 9.375f, 6.875f, 18.25f, 13.75f, 30.375f, 50.125f};
__device__ __constant__ float c_awl[3] = {1.5f, 2.375f, 5.f};
__device__ __constant__ float c_ahl[3] = {2.f, 4.5f, 3.5f};

#define BOX_RATIO 0.05
#define CLS_RATIO 1.0
#define BALANCE_L 4.0
#define OBJ_RATIO (5.0 * 608.0 * 608.0 / (416.0 * 416.0))

// ---------------- device scratch (zero-initialized at load; self-reset per call) ----------------
__device__ double g_bk_conf[NBANK];
__device__ double g_bk_loc[NBANK];
__device__ double g_bk_cls[NBANK];
__device__ int    g_bk_mask[NBANK];
__device__ int    g_nobj = 0;
__device__ int    g_done = 0;

__device__ __forceinline__ float sigfast(float x) { return __fdividef(1.f, 1.f + __expf(-x)); }
// softplus(x) = bce(sigmoid(x), 0);  bce(sigmoid(x), 1) = softplus(-x)
__device__ __forceinline__ float splus(float x) { return __logf(1.f + __expf(x)); }

struct SMatch { int a, gi, gj, cls; float gx, gy, gw, gh; };

// ---------------- single fused kernel ----------------
// grid (NVB+1, BS): x < NVB -> dense conf pass (2 cells/thread), x == NVB -> match+correction.
__global__ void __launch_bounds__(256, 5) k_fused(const float* __restrict__ input,
                                                  const float* __restrict__ targets,
                                                  float* __restrict__ out) {
    const int b = blockIdx.y;
    const int tid = threadIdx.x;
    const int wid = tid >> 5, lane = tid & 31;
    const int bank = (b * (NVB + 1) + blockIdx.x) & (NBANK - 1);

    if (blockIdx.x == NVB) {
        // ======== match + correction block for batch item b ========
        __shared__ float sminx[NT], smaxx[NT], sminy[NT], smaxy[NT], sarea[NT];
        __shared__ int s_flat[NT];
        __shared__ int s_cnt;
        __shared__ SMatch s_m[NT];
        __shared__ double s_conf, s_loc, s_cls;
        __shared__ int s_mask;
        if (tid == 0) { s_cnt = 0; s_conf = 0.0; s_loc = 0.0; s_cls = 0.0; s_mask = 0; }
        __syncthreads();

        int flat = -1, bn = 0, gi = 0, gj = 0;
        float x = 0.f, y = 0.f, w = 0.f, h = 0.f;
        if (tid < NT) {
            const float* tp = targets + (b * NT + tid) * 5;
            x = tp[0] * (float)IN_W;
            y = tp[1] * (float)IN_H;
            w = tp[2] * (float)IN_W;
            h = tp[3] * (float)IN_H;
            sminx[tid] = x - w * 0.5f; smaxx[tid] = x + w * 0.5f;
            sminy[tid] = y - h * 0.5f; smaxy[tid] = y + h * 0.5f;
            sarea[tid] = w * h;
            float best = -1.f;
            #pragma unroll
            for (int a = 0; a < 9; a++) {
                float inter = fminf(w, c_aw9[a]) * fminf(h, c_ah9[a]);
                float uni   = w * h + c_aw9[a] * c_ah9[a] - inter;
                float r = inter / uni;
                if (r > best) { best = r; bn = a; }
            }
            if (bn < NA) {   // ANCHORS_MASK[2] = [0,1,2]
                gi = min(max((int)floorf(x), 0), IN_W - 1);
                gj = min(max((int)floorf(y), 0), IN_H - 1);
                flat = (bn * IN_H + gj) * IN_W + gi;
            }
            s_flat[tid] = flat;
        }
        __syncthreads();
        if (tid < NT && flat >= 0) {
            // last-wins dedupe
            bool fin = true;
            for (int t2 = tid + 1; t2 < NT; t2++)
                if (s_flat[t2] == flat) { fin = false; break; }
            if (fin) {
                int idx = atomicAdd(&s_cnt, 1);
                SMatch m; m.a = bn; m.gi = gi; m.gj = gj;
                m.gx = x; m.gy = y; m.gw = w; m.gh = h;
                m.cls = (int)targets[(b * NT + tid) * 5 + 4];
                s_m[idx] = m;
            }
        }
        __syncthreads();

        const int cnt = s_cnt;
        for (int c = wid; c < cnt; c += 8) {
            SMatch M = s_m[c];
            const float* base = input + ((size_t)b * 255 + (size_t)M.a * 85) * PLANE
                                      + (size_t)M.gj * IN_W + M.gi;

            float v5 = (lane < 5) ? base[(size_t)lane * PLANE] : 0.f;
            float tx = __shfl_sync(0xffffffffu, v5, 0);
            float ty = __shfl_sync(0xffffffffu, v5, 1);
            float tw = __shfl_sync(0xffffffffu, v5, 2);
            float th = __shfl_sync(0xffffffffu, v5, 3);
            float tc = __shfl_sync(0xffffffffu, v5, 4);

            float clssum = 0.f;
            #pragma unroll
            for (int cc = lane; cc < NC; cc += 32) {
                float tv = base[(size_t)(5 + cc) * PLANE];
                clssum += (cc == M.cls) ? splus(-tv) : splus(tv);
            }

            float px = (float)M.gi + sigfast(tx);
            float py = (float)M.gj + sigfast(ty);
            float pw = __expf(tw) * c_awl[M.a];
            float ph = __expf(th) * c_ahl[M.a];
            float b1minx = px - pw * 0.5f, b1maxx = px + pw * 0.5f;
            float b1miny = py - ph * 0.5f, b1maxy = py + ph * 0.5f;
            float pa = pw * ph;

            // ignore-IoU vs 20 gt boxes — same scalar sequence as dense path
            bool hit_t = false;
            if (lane < NT) {
                float ia = fminf(smaxx[lane], b1maxx);
                float ib = fmaxf(sminx[lane], b1minx);
                float iw2 = fmaxf(ia - ib, 0.f);
                float ca = fminf(smaxy[lane], b1maxy);
                float cb = fmaxf(sminy[lane], b1miny);
                float ih2 = ca - cb;
                float diff = fmaf(iw2 * ih2, 3.f, -sarea[lane]);
                hit_t = diff > pa;
            }
            unsigned hitmask = __ballot_sync(0xffffffffu, hit_t);
            #pragma unroll
            for (int o = 16; o > 0; o >>= 1)
                clssum += __shfl_down_sync(0xffffffffu, clssum, o);

            if (lane == 0) {
                // ---- CIoU (exact reference math) ----
                float b2minx = M.gx - M.gw * 0.5f, b2maxx = M.gx + M.gw * 0.5f;
                float b2miny = M.gy - M.gh * 0.5f, b2maxy = M.gy + M.gh * 0.5f;
                float iw = fmaxf(fminf(b1maxx, b2maxx) - fmaxf(b1minx, b2minx), 0.f);
                float ih = fmaxf(fminf(b1maxy, b2maxy) - fmaxf(b1miny, b2miny), 0.f);
                float inter = iw * ih;
                float a2 = M.gw * M.gh;
                float iou = inter / fmaxf(pa + a2 - inter, 1e-6f);
                float cdx = px - M.gx, cdy = py - M.gy;
                float center_d = cdx * cdx + cdy * cdy;
                float ew = fmaxf(fmaxf(b1maxx, b2maxx) - fminf(b1minx, b2minx), 0.f);
                float eh = fmaxf(fmaxf(b1maxy, b2maxy) - fminf(b1miny, b2miny), 0.f);
                float encl = ew * ew + eh * eh;
                float ciou = iou - center_d / fmaxf(encl, 1e-6f);
                const float FOUR_OVER_PI2 = 4.f / (float)(M_PI * M_PI);
                float dat = atanf(pw / fmaxf(ph, 1e-6f)) - atanf(M.gw / fmaxf(M.gh, 1e-6f));
                float v = FOUR_OVER_PI2 * dat * dat;
                float alpha = v / fmaxf(1.f - iou + v, 1e-6f);
                ciou = ciou - alpha * v;

                // ---- conf correction (exact cancel vs dense pass) ----
                float noobj0 = hitmask ? 0.f : 1.f;
                float add = splus(-tc);
                float sub = splus(tc) * noobj0;

                atomicAdd(&s_conf, (double)(add - sub));
                atomicAdd(&s_mask, (int)(1.f - noobj0));
                atomicAdd(&s_loc,  (double)(1.f - ciou));
                atomicAdd(&s_cls,  (double)clssum);
            }
        }
        __syncthreads();
        if (tid == 0) {
            atomicAdd(&g_bk_conf[bank], s_conf);
            atomicAdd(&g_bk_mask[bank], s_mask);
            atomicAdd(&g_bk_loc[bank],  s_loc);
            atomicAdd(&g_bk_cls[bank],  s_cls);
            atomicAdd(&g_nobj, cnt);
        }
    } else {
        // ======== dense conf block: 2 cells/thread, strength-reduced IoU test ========
        __shared__ float4 s_box[NT];  // {minx, maxx, miny, maxy}
        __shared__ float  s_nt[NT];   // -area
        if (tid < NT) {
            const float* tp = targets + (b * NT + tid) * 5;
            float gx = tp[0] * (float)IN_W, gy = tp[1] * (float)IN_H;
            float gw = tp[2] * (float)IN_W, gh = tp[3] * (float)IN_H;
            s_box[tid] = make_float4(gx - gw * 0.5f, gx + gw * 0.5f,
                                     gy - gh * 0.5f, gy + gh * 0.5f);
            s_nt[tid] = -(gw * gh);
        }
        __syncthreads();

        float cnum = 0.f;
        int cmask = 0;
        const int v = blockIdx.x * 256 + tid;
        if (v < VCELLS2) {
            const int m0  = v * 2;
            const int a   = m0 / PLANE;
            const int rem = m0 - a * PLANE;
            const int i   = rem / IN_W;
            const int j   = rem - i * IN_W;

            const float* base = input + ((size_t)b * 255 + (size_t)a * 85) * PLANE + rem;
            float2 tx = *(const float2*)(base);
            float2 ty = *(const float2*)(base + PLANE);
            float2 tw = *(const float2*)(base + 2 * PLANE);
            float2 th = *(const float2*)(base + 3 * PLANE);
            float2 tc = *(const float2*)(base + 4 * PLANE);

            float mnx[2], mxx[2], mny[2], mxy[2], pa[2], maxd[2];
            const float tcv[2] = {tc.x, tc.y};
            {
                const float txa[2] = {tx.x, tx.y};
                const float tya[2] = {ty.x, ty.y};
                const float twa[2] = {tw.x, tw.y};
                const float tha[2] = {th.x, th.y};
                #pragma unroll
                for (int k = 0; k < 2; k++) {
                    float px = (float)(j + k) + sigfast(txa[k]);
                    float py = (float)i       + sigfast(tya[k]);
                    float pw = __expf(twa[k]) * c_awl[a];
                    float ph = __expf(tha[k]) * c_ahl[a];
                    mnx[k] = px - pw * 0.5f; mxx[k] = px + pw * 0.5f;
                    mny[k] = py - ph * 0.5f; mxy[k] = py + ph * 0.5f;
                    pa[k] = pw * ph;
                    maxd[k] = -1e30f;
                }
            }

            // maxd[k] = max_t (3*inter - tar);  hit iff maxd > pa (pa const per cell)
            #pragma unroll
            for (int t = 0; t < NT; t++) {
                const float4 B = s_box[t];       // one LDS.128
                const float nt = s_nt[t];        // one LDS.32
                #pragma unroll
                for (int k = 0; k < 2; k++) {
                    float ia = fminf(B.y, mxx[k]);
                    float ib = fmaxf(B.x, mnx[k]);
                    float iw = fmaxf(ia - ib, 0.f);
                    float ca = fminf(B.w, mxy[k]);
                    float cb = fmaxf(B.z, mny[k]);
                    float ih = ca - cb;          // no clamp: if neg, iw>=0 => diff loses max
                    float diff = fmaf(iw * ih, 3.f, nt);
                    maxd[k] = fmaxf(maxd[k], diff);
                }
            }
            #pragma unroll
            for (int k = 0; k < 2; k++) {
                if (maxd[k] <= pa[k]) {          // noobj
                    cnum  += splus(tcv[k]);
                    cmask += 1;
                }
            }
        }

        #pragma unroll
        for (int o = 16; o > 0; o >>= 1) {
            cnum  += __shfl_down_sync(0xffffffffu, cnum,  o);
            cmask += __shfl_down_sync(0xffffffffu, cmask, o);
        }
        __shared__ float rn[8];
        __shared__ int   rm[8];
        if (lane == 0) { rn[wid] = cnum; rm[wid] = cmask; }
        __syncthreads();
        if (wid == 0) {
            float n = (lane < 8) ? rn[lane] : 0.f;
            int   k = (lane < 8) ? rm[lane] : 0;
            #pragma unroll
            for (int o = 4; o > 0; o >>= 1) {
                n += __shfl_down_sync(0xffffffffu, n, o);
                k += __shfl_down_sync(0xffffffffu, k, o);
            }
            if (lane == 0) {
                atomicAdd(&g_bk_conf[bank], (double)n);
                atomicAdd(&g_bk_mask[bank], k);
            }
        }
        __syncthreads();
    }

    // ======== grid-wide completion: last block's warp 0 assembles the loss ========
    if (wid == 0) {
        int d = 0;
        if (lane == 0) { __threadfence(); d = atomicAdd(&g_done, 1); }
        d = __shfl_sync(0xffffffffu, d, 0);
        if (d == TOTAL_BLOCKS - 1) {
            __threadfence();
            double vconf = 0.0, vloc = 0.0, vcls = 0.0;
            int vmask = 0;
            if (lane < NBANK) {
                vconf = g_bk_conf[lane];
                vloc  = g_bk_loc[lane];
                vcls  = g_bk_cls[lane];
                vmask = g_bk_mask[lane];
                // reset banks for the next graph replay
                g_bk_conf[lane] = 0.0; g_bk_loc[lane] = 0.0;
                g_bk_cls[lane]  = 0.0; g_bk_mask[lane] = 0;
            }
            #pragma unroll
            for (int o = 8; o > 0; o >>= 1) {
                vconf += __shfl_down_sync(0xffffffffu, vconf, o);
                vloc  += __shfl_down_sync(0xffffffffu, vloc,  o);
                vcls  += __shfl_down_sync(0xffffffffu, vcls,  o);
                vmask += __shfl_down_sync(0xffffffffu, vmask, o);
            }
            if (lane == 0) {
                int nobj_i = g_nobj;
                double nobj = (nobj_i > 0) ? (double)nobj_i : 1.0;
                double msum = (double)vmask;
                double loss = vloc / nobj * BOX_RATIO
                            + vcls / (nobj * (double)NC) * CLS_RATIO
                            + vconf / fmax(msum, 1.0) * BALANCE_L * OBJ_RATIO;
                out[0] = (float)loss;
                g_nobj = 0; g_done = 0;
            }
        }
    }
}

// ---------------- launcher ----------------
extern "C" void kernel_launch(void* const* d_in, const int* in_sizes, int n_in,
                              void* d_out, int out_size) {
    const float* input   = (const float*)d_in[0];
    const float* targets = (const float*)d_in[1];
    float* out = (float*)d_out;
    (void)in_sizes; (void)n_in; (void)out_size;

    dim3 grid(NVB + 1, BS);
    k_fused<<<grid, 256>>>(input, targets, out);
}

// round 11
// speedup vs baseline: 1.5000x; 1.5000x over previous
#include <cuda_runtime.h>
#include <cuda_fp16.h>
#include <math.h>
#include <stdint.h>

// ---------------- problem constants (l = 2, 76x76 head) ----------------
#define IN_H   76
#define IN_W   76
#define PLANE  (IN_H * IN_W)        // 5776 (even)
#define BS     32
#define NT     20
#define NA     3
#define NC     80
#define CELLS  (NA * PLANE)         // 17328 per batch item
#define VCELLS2 (CELLS / 2)         // 8664 float2 groups per batch item
#define NVB    ((VCELLS2 + 255) / 256)  // 34 dense x-blocks
#define TOTAL_BLOCKS ((NVB + 1) * BS)   // 1120

__device__ __constant__ float c_aw9[9] = {1.5f, 2.375f, 5.f, 4.5f, 9.5f, 9.f, 17.75f, 24.f, 57.375f};
__device__ __constant__ float c_ah9[9] = {2.f, 4.5f, 3.5f, 9.375f, 6.875f, 18.25f, 13.75f, 30.375f, 50.125f};
__device__ __constant__ float c_awl[3] = {1.5f, 2.375f, 5.f};
__device__ __constant__ float c_ahl[3] = {2.f, 4.5f, 3.5f};

#define BOX_RATIO 0.05
#define CLS_RATIO 1.0
#define BALANCE_L 4.0
#define OBJ_RATIO (5.0 * 608.0 * 608.0 / (416.0 * 416.0))

// ---------------- device scratch (zero-initialized at load; self-reset per call) ----------------
__device__ double g_conf_num = 0.0;
__device__ double g_mask_sum = 0.0;
__device__ double g_loc_sum  = 0.0;
__device__ double g_cls_sum  = 0.0;
__device__ int    g_nobj     = 0;
__device__ int    g_done     = 0;

__device__ __forceinline__ float sigfast(float x) { return __fdividef(1.f, 1.f + __expf(-x)); }
// softplus(x) = bce(sigmoid(x), 0);  bce(sigmoid(x), 1) = softplus(-x)
__device__ __forceinline__ float splus(float x) { return __logf(1.f + __expf(x)); }

struct SMatch { int a, gi, gj, cls; float gx, gy, gw, gh; };
struct __align__(16) TBox { __half2 mnx, mxx, mny, mxy; };   // duplicated target bounds

// ---------------- single fused kernel ----------------
// grid (NVB+1, BS): x < NVB -> dense conf pass (2 cells/thread, fp16x2 ignore test),
//                   x == NVB -> match + correction (identical fp16 predicate).
__global__ void __launch_bounds__(256, 5) k_fused(const float* __restrict__ input,
                                                  const float* __restrict__ targets,
                                                  float* __restrict__ out) {
    const int b = blockIdx.y;
    const int tid = threadIdx.x;
    const int wid = tid >> 5, lane = tid & 31;

    if (blockIdx.x == NVB) {
        // ======== match + correction block for batch item b ========
        __shared__ float sminx[NT], smaxx[NT], sminy[NT], smaxy[NT], sarea[NT];
        __shared__ int s_flat[NT];
        __shared__ int s_cnt;
        __shared__ SMatch s_m[NT];
        __shared__ double s_conf, s_mask, s_loc, s_cls;
        if (tid == 0) { s_cnt = 0; s_conf = 0.0; s_mask = 0.0; s_loc = 0.0; s_cls = 0.0; }
        __syncthreads();

        int flat = -1, bn = 0, gi = 0, gj = 0;
        float x = 0.f, y = 0.f, w = 0.f, h = 0.f;
        if (tid < NT) {
            const float* tp = targets + (b * NT + tid) * 5;
            x = tp[0] * (float)IN_W;
            y = tp[1] * (float)IN_H;
            w = tp[2] * (float)IN_W;
            h = tp[3] * (float)IN_H;
            sminx[tid] = x - w * 0.5f; smaxx[tid] = x + w * 0.5f;
            sminy[tid] = y - h * 0.5f; smaxy[tid] = y + h * 0.5f;
            sarea[tid] = w * h;
            float best = -1.f;
            #pragma unroll
            for (int a = 0; a < 9; a++) {
                float inter = fminf(w, c_aw9[a]) * fminf(h, c_ah9[a]);
                float uni   = w * h + c_aw9[a] * c_ah9[a] - inter;
                float r = inter / uni;
                if (r > best) { best = r; bn = a; }
            }
            if (bn < NA) {   // ANCHORS_MASK[2] = [0,1,2]
                gi = min(max((int)floorf(x), 0), IN_W - 1);
                gj = min(max((int)floorf(y), 0), IN_H - 1);
                flat = (bn * IN_H + gj) * IN_W + gi;
            }
            s_flat[tid] = flat;
        }
        __syncthreads();
        if (tid < NT && flat >= 0) {
            // last-wins dedupe
            bool fin = true;
            for (int t2 = tid + 1; t2 < NT; t2++)
                if (s_flat[t2] == flat) { fin = false; break; }
            if (fin) {
                int idx = atomicAdd(&s_cnt, 1);
                SMatch m; m.a = bn; m.gi = gi; m.gj = gj;
                m.gx = x; m.gy = y; m.gw = w; m.gh = h;
                m.cls = (int)targets[(b * NT + tid) * 5 + 4];
                s_m[idx] = m;
            }
        }
        __syncthreads();

        const int cnt = s_cnt;
        for (int c = wid; c < cnt; c += 8) {
            SMatch M = s_m[c];
            const float* base = input + ((size_t)b * 255 + (size_t)M.a * 85) * PLANE
                                      + (size_t)M.gj * IN_W + M.gi;

            float v5 = (lane < 5) ? base[(size_t)lane * PLANE] : 0.f;
            float tx = __shfl_sync(0xffffffffu, v5, 0);
            float ty = __shfl_sync(0xffffffffu, v5, 1);
            float tw = __shfl_sync(0xffffffffu, v5, 2);
            float th = __shfl_sync(0xffffffffu, v5, 3);
            float tc = __shfl_sync(0xffffffffu, v5, 4);

            float clssum = 0.f;
            #pragma unroll
            for (int cc = lane; cc < NC; cc += 32) {
                float tv = base[(size_t)(5 + cc) * PLANE];
                clssum += (cc == M.cls) ? splus(-tv) : splus(tv);
            }

            float px = (float)M.gi + sigfast(tx);
            float py = (float)M.gj + sigfast(ty);
            float pw = __expf(tw) * c_awl[M.a];
            float ph = __expf(th) * c_ahl[M.a];
            float b1minx = px - pw * 0.5f, b1maxx = px + pw * 0.5f;
            float b1miny = py - ph * 0.5f, b1maxy = py + ph * 0.5f;
            float pa = pw * ph;

            // ignore-IoU vs 20 gt boxes — half2 sequence IDENTICAL to dense path
            bool hit_t = false;
            if (lane < NT) {
                __half2 tmnx = __floats2half2_rn(sminx[lane], sminx[lane]);
                __half2 tmxx = __floats2half2_rn(smaxx[lane], smaxx[lane]);
                __half2 tmny = __floats2half2_rn(sminy[lane], sminy[lane]);
                __half2 tmxy = __floats2half2_rn(smaxy[lane], smaxy[lane]);
                __half2 nt2  = __floats2half2_rn(-sarea[lane], -sarea[lane]);
                __half2 cmnx = __floats2half2_rn(b1minx, b1minx);
                __half2 cmxx = __floats2half2_rn(b1maxx, b1maxx);
                __half2 cmny = __floats2half2_rn(b1miny, b1miny);
                __half2 cmxy = __floats2half2_rn(b1maxy, b1maxy);
                const __half2 zero2  = __floats2half2_rn(0.f, 0.f);
                const __half2 three2 = __floats2half2_rn(3.f, 3.f);
                __half2 iw2h = __hmax2(__hsub2(__hmin2(tmxx, cmxx), __hmax2(tmnx, cmnx)), zero2);
                __half2 ih2h = __hsub2(__hmin2(tmxy, cmxy), __hmax2(tmny, cmny));
                __half2 diff = __hfma2(__hmul2(iw2h, ih2h), three2, nt2);
                hit_t = __hgt(__low2half(diff), __float2half_rn(pa));
            }
            unsigned hitmask = __ballot_sync(0xffffffffu, hit_t);
            #pragma unroll
            for (int o = 16; o > 0; o >>= 1)
                clssum += __shfl_down_sync(0xffffffffu, clssum, o);

            if (lane == 0) {
                // ---- CIoU (exact reference math, fp32) ----
                float b2minx = M.gx - M.gw * 0.5f, b2maxx = M.gx + M.gw * 0.5f;
                float b2miny = M.gy - M.gh * 0.5f, b2maxy = M.gy + M.gh * 0.5f;
                float iw = fmaxf(fminf(b1maxx, b2maxx) - fmaxf(b1minx, b2minx), 0.f);
                float ih = fmaxf(fminf(b1maxy, b2maxy) - fmaxf(b1miny, b2miny), 0.f);
                float inter = iw * ih;
                float a2 = M.gw * M.gh;
                float iou = inter / fmaxf(pa + a2 - inter, 1e-6f);
                float cdx = px - M.gx, cdy = py - M.gy;
                float center_d = cdx * cdx + cdy * cdy;
                float ew = fmaxf(fmaxf(b1maxx, b2maxx) - fminf(b1minx, b2minx), 0.f);
                float eh = fmaxf(fmaxf(b1maxy, b2maxy) - fminf(b1miny, b2miny), 0.f);
                float encl = ew * ew + eh * eh;
                float ciou = iou - center_d / fmaxf(encl, 1e-6f);
                const float FOUR_OVER_PI2 = 4.f / (float)(M_PI * M_PI);
                float dat = atanf(pw / fmaxf(ph, 1e-6f)) - atanf(M.gw / fmaxf(M.gh, 1e-6f));
                float v = FOUR_OVER_PI2 * dat * dat;
                float alpha = v / fmaxf(1.f - iou + v, 1e-6f);
                ciou = ciou - alpha * v;

                // ---- conf correction (exact cancel vs dense pass) ----
                float noobj0 = hitmask ? 0.f : 1.f;
                float add = splus(-tc);
                float sub = splus(tc) * noobj0;

                atomicAdd(&s_conf, (double)(add - sub));
                atomicAdd(&s_mask, (double)(1.f - noobj0));
                atomicAdd(&s_loc,  (double)(1.f - ciou));
                atomicAdd(&s_cls,  (double)clssum);
            }
        }
        __syncthreads();
        if (tid == 0) {
            atomicAdd(&g_conf_num, s_conf);
            atomicAdd(&g_mask_sum, s_mask);
            atomicAdd(&g_loc_sum,  s_loc);
            atomicAdd(&g_cls_sum,  s_cls);
            atomicAdd(&g_nobj, cnt);
        }
    } else {
        // ======== dense conf block: 2 cells/thread, half2-packed ignore test ========
        __shared__ TBox   s_tb[NT];
        __shared__ __half2 s_nt2[NT];   // -area duplicated
        if (tid < NT) {
            const float* tp = targets + (b * NT + tid) * 5;
            float gx = tp[0] * (float)IN_W, gy = tp[1] * (float)IN_H;
            float gw = tp[2] * (float)IN_W, gh = tp[3] * (float)IN_H;
            float mnx = gx - gw * 0.5f, mxx = gx + gw * 0.5f;
            float mny = gy - gh * 0.5f, mxy = gy + gh * 0.5f;
            TBox tb;
            tb.mnx = __floats2half2_rn(mnx, mnx);
            tb.mxx = __floats2half2_rn(mxx, mxx);
            tb.mny = __floats2half2_rn(mny, mny);
            tb.mxy = __floats2half2_rn(mxy, mxy);
            s_tb[tid] = tb;
            s_nt2[tid] = __floats2half2_rn(-(gw * gh), -(gw * gh));
        }
        __syncthreads();

        float cnum = 0.f, cmask = 0.f;
        const int v = blockIdx.x * 256 + tid;
        if (v < VCELLS2) {
            const int m0  = v * 2;
            const int a   = m0 / PLANE;
            const int rem = m0 - a * PLANE;
            const int i   = rem / IN_W;
            const int j   = rem - i * IN_W;

            const float* base = input + ((size_t)b * 255 + (size_t)a * 85) * PLANE + rem;
            float2 tx = *(const float2*)(base);
            float2 ty = *(const float2*)(base + PLANE);
            float2 tw = *(const float2*)(base + 2 * PLANE);
            float2 th = *(const float2*)(base + 3 * PLANE);
            float2 tc = *(const float2*)(base + 4 * PLANE);

            float mnx[2], mxx[2], mny[2], mxy[2], pa[2];
            const float tcv[2] = {tc.x, tc.y};
            {
                const float txa[2] = {tx.x, tx.y};
                const float tya[2] = {ty.x, ty.y};
                const float twa[2] = {tw.x, tw.y};
                const float tha[2] = {th.x, th.y};
                #pragma unroll
                for (int k = 0; k < 2; k++) {
                    float px = (float)(j + k) + sigfast(txa[k]);
                    float py = (float)i       + sigfast(tya[k]);
                    float pw = __expf(twa[k]) * c_awl[a];
                    float ph = __expf(tha[k]) * c_ahl[a];
                    mnx[k] = px - pw * 0.5f; mxx[k] = px + pw * 0.5f;
                    mny[k] = py - ph * 0.5f; mxy[k] = py + ph * 0.5f;
                    pa[k] = pw * ph;
                }
            }
            // pack: lo = cell0, hi = cell1
            __half2 cmnx = __floats2half2_rn(mnx[0], mnx[1]);
            __half2 cmxx = __floats2half2_rn(mxx[0], mxx[1]);
            __half2 cmny = __floats2half2_rn(mny[0], mny[1]);
            __half2 cmxy = __floats2half2_rn(mxy[0], mxy[1]);
            const __half2 zero2  = __floats2half2_rn(0.f, 0.f);
            const __half2 three2 = __floats2half2_rn(3.f, 3.f);
            __half2 maxd = __floats2half2_rn(-60000.f, -60000.f);

            #pragma unroll
            for (int t = 0; t < NT; t++) {
                TBox tb = s_tb[t];                      // LDS.128
                __half2 nt2 = s_nt2[t];                 // LDS.32
                __half2 iw2h = __hmax2(__hsub2(__hmin2(tb.mxx, cmxx), __hmax2(tb.mnx, cmnx)), zero2);
                __half2 ih2h = __hsub2(__hmin2(tb.mxy, cmxy), __hmax2(tb.mny, cmny));
                __half2 diff = __hfma2(__hmul2(iw2h, ih2h), three2, nt2);
                maxd = __hmax2(maxd, diff);
            }

            const bool hit0 = __hgt(__low2half(maxd),  __float2half_rn(pa[0]));
            const bool hit1 = __hgt(__high2half(maxd), __float2half_rn(pa[1]));
            if (!hit0) { cnum += splus(tcv[0]); cmask += 1.f; }
            if (!hit1) { cnum += splus(tcv[1]); cmask += 1.f; }
        }

        #pragma unroll
        for (int o = 16; o > 0; o >>= 1) {
            cnum  += __shfl_down_sync(0xffffffffu, cnum,  o);
            cmask += __shfl_down_sync(0xffffffffu, cmask, o);
        }
        __shared__ float rn[8], rm[8];
        if (lane == 0) { rn[wid] = cnum; rm[wid] = cmask; }
        __syncthreads();
        if (wid == 0) {
            float n = (lane < 8) ? rn[lane] : 0.f;
            float k = (lane < 8) ? rm[lane] : 0.f;
            #pragma unroll
            for (int o = 4; o > 0; o >>= 1) {
                n += __shfl_down_sync(0xffffffffu, n, o);
                k += __shfl_down_sync(0xffffffffu, k, o);
            }
            if (lane == 0) {
                atomicAdd(&g_conf_num, (double)n);
                atomicAdd(&g_mask_sum, (double)k);
            }
        }
        __syncthreads();
    }

    // ======== grid-wide completion: last block assembles the loss ========
    if (tid == 0) {
        __threadfence();
        int d = atomicAdd(&g_done, 1);
        if (d == TOTAL_BLOCKS - 1) {
            double nobj = (g_nobj > 0) ? (double)g_nobj : 1.0;
            double loss = g_loc_sum / nobj * BOX_RATIO
                        + g_cls_sum / (nobj * (double)NC) * CLS_RATIO
                        + g_conf_num / fmax(g_mask_sum, 1.0) * BALANCE_L * OBJ_RATIO;
            out[0] = (float)loss;
            // self-reset for the next graph replay
            g_conf_num = 0.0; g_mask_sum = 0.0; g_loc_sum = 0.0; g_cls_sum = 0.0;
            g_nobj = 0; g_done = 0;
        }
    }
}

// ---------------- launcher ----------------
extern "C" void kernel_launch(void* const* d_in, const int* in_sizes, int n_in,
                              void* d_out, int out_size) {
    const float* input   = (const float*)d_in[0];
    const float* targets = (const float*)d_in[1];
    float* out = (float*)d_out;
    (void)in_sizes; (void)n_in; (void)out_size;

    dim3 grid(NVB + 1, BS);
    k_fused<<<grid, 256>>>(input, targets, out);
}